// round 11
// baseline (speedup 1.0000x reference)
#include <cuda_runtime.h>
#include <math.h>

#define NN   4096
#define DD   512
#define F1C  64
#define HC   4
#define HF   256   // HC*F1C
#define F2C  32
#define F3C  16
#define MAXD 128

// packed fp32x2 FMA (Blackwell)
#define FMA_F32X2(d, a, b, c) \
    asm("fma.rn.f32x2 %0, %1, %2, %3;" : "=l"(d) : "l"(a), "l"(b), "l"(c))
#define PACK2(out, lo, hi) \
    asm("mov.b64 %0, {%1, %2};" : "=l"(out) : "r"(lo), "r"(hi))
#define UNPACK2(lo, hi, in) \
    asm("mov.b64 {%0, %1}, %2;" : "=r"(lo), "=r"(hi) : "l"(in))

__device__ __forceinline__ float4 unpack4(ulonglong2 a) {
    unsigned u0, u1, u2, u3;
    UNPACK2(u0, u1, a.x);
    UNPACK2(u2, u3, a.y);
    return make_float4(__uint_as_float(u0), __uint_as_float(u1),
                       __uint_as_float(u2), __uint_as_float(u3));
}

// ---------------- scratch ---------------------------------------------------
__device__ int    g_deg[NN];
__device__ int    g_cols[NN * MAXD];
__device__ float  g_WhAll[NN * HF];      // [i][h*64+f]
__device__ float  g_s1h[HC * NN];        // [head][row]
__device__ float  g_s2h[HC * NN];
__device__ float  g_cat[NN * HF];
__device__ float  g_Wh2[NN * F1C];
__device__ float  g_s1b[NN];
__device__ float  g_s2b[NN];
__device__ float  g_t1[NN * F2C];
__device__ float  g_t2[NN * F3C];
__device__ float  g_t3[NN * F3C];
__device__ float  g_z[NN * F3C];

// ============ fused: blocks [0,256) GEMM1 tiles, [256,768) build ELL ========
__global__ void k_build_gemm1(const float* __restrict__ adj,
                              const float* __restrict__ x,
                              const float* __restrict__ W_heads,
                              const float* __restrict__ a_heads) {
    __shared__ __align__(16) float sA[16][64];
    __shared__ __align__(16) float sB[16][64];
    int bx = blockIdx.x;
    if (bx >= 256) {
        // ---- adjacency build: warp per row (float4 scan + ballot compact) --
        int wb = bx - 256;
        int row = wb * 8 + (threadIdx.x >> 5);
        int lane = threadIdx.x & 31;
        const float4* arow = (const float4*)(adj + (size_t)row * NN);
        int cnt = 0;
        for (int j0 = 0; j0 < NN; j0 += 128) {
            float4 v = arow[(j0 >> 2) + lane];
            int base = j0 + lane * 4;
#pragma unroll
            for (int c = 0; c < 4; c++) {
                float val = (c == 0) ? v.x : (c == 1) ? v.y : (c == 2) ? v.z : v.w;
                unsigned m = __ballot_sync(0xffffffffu, val > 0.f);
                if (val > 0.f) {
                    int pos = cnt + __popc(m & ((1u << lane) - 1u));
                    if (pos < MAXD) g_cols[row * MAXD + pos] = base + c;
                }
                cnt += __popc(m);
            }
        }
        if (lane == 0) g_deg[row] = cnt < MAXD ? cnt : MAXD;
        return;
    }
    // ---- GEMM1 tile: head = bx>>6, row-block = bx&63 -----------------------
    int head = bx >> 6;
    int bm = (bx & 63) << 6;
    int tid = threadIdx.x;
    int ty = tid >> 4, tx = tid & 15;
    const float* B = W_heads + (size_t)head * DD * F1C;
    unsigned long long acc2[4][2] = {};
    for (int k0 = 0; k0 < DD; k0 += 16) {
        int ar = tid >> 2, kq = (tid & 3) << 2;
        float4 va = *(const float4*)(x + (size_t)(bm + ar) * DD + k0 + kq);
        sA[kq + 0][ar] = va.x; sA[kq + 1][ar] = va.y;
        sA[kq + 2][ar] = va.z; sA[kq + 3][ar] = va.w;
        int br = tid >> 4, nq = (tid & 15) << 2;
        *(float4*)&sB[br][nq] = *(const float4*)(B + (size_t)(k0 + br) * F1C + nq);
        __syncthreads();
#pragma unroll
        for (int kk = 0; kk < 16; kk++) {
            float4 av = *(const float4*)&sA[kk][ty << 2];
            ulonglong2 bb = *(const ulonglong2*)&sB[kk][tx << 2];
            unsigned long long ap;
            PACK2(ap, __float_as_uint(av.x), __float_as_uint(av.x));
            FMA_F32X2(acc2[0][0], ap, bb.x, acc2[0][0]);
            FMA_F32X2(acc2[0][1], ap, bb.y, acc2[0][1]);
            PACK2(ap, __float_as_uint(av.y), __float_as_uint(av.y));
            FMA_F32X2(acc2[1][0], ap, bb.x, acc2[1][0]);
            FMA_F32X2(acc2[1][1], ap, bb.y, acc2[1][1]);
            PACK2(ap, __float_as_uint(av.z), __float_as_uint(av.z));
            FMA_F32X2(acc2[2][0], ap, bb.x, acc2[2][0]);
            FMA_F32X2(acc2[2][1], ap, bb.y, acc2[2][1]);
            PACK2(ap, __float_as_uint(av.w), __float_as_uint(av.w));
            FMA_F32X2(acc2[3][0], ap, bb.x, acc2[3][0]);
            FMA_F32X2(acc2[3][1], ap, bb.y, acc2[3][1]);
        }
        __syncthreads();
    }
    float acc[4][4];
#pragma unroll
    for (int i = 0; i < 4; i++) {
        float4 t = unpack4(*(ulonglong2*)acc2[i]);
        acc[i][0] = t.x; acc[i][1] = t.y; acc[i][2] = t.z; acc[i][3] = t.w;
    }
#pragma unroll
    for (int i = 0; i < 4; i++) {
        float4 v = make_float4(acc[i][0], acc[i][1], acc[i][2], acc[i][3]);
        *(float4*)(g_WhAll + (size_t)(bm + ty * 4 + i) * HF + head * F1C + (tx << 2)) = v;
    }
    // score epilogue
    const float* ag = a_heads + head * 2 * F1C;
    float a1v[4], a2v[4];
#pragma unroll
    for (int c = 0; c < 4; c++) { a1v[c] = ag[(tx << 2) + c]; a2v[c] = ag[F1C + (tx << 2) + c]; }
#pragma unroll
    for (int i = 0; i < 4; i++) {
        float p1 = acc[i][0] * a1v[0] + acc[i][1] * a1v[1] + acc[i][2] * a1v[2] + acc[i][3] * a1v[3];
        float p2 = acc[i][0] * a2v[0] + acc[i][1] * a2v[1] + acc[i][2] * a2v[2] + acc[i][3] * a2v[3];
#pragma unroll
        for (int o = 8; o; o >>= 1) {
            p1 += __shfl_xor_sync(0xffffffffu, p1, o);
            p2 += __shfl_xor_sync(0xffffffffu, p2, o);
        }
        if (tx == 0) {
            int row = bm + ty * 4 + i;
            g_s1h[head * NN + row] = p1;
            g_s2h[head * NN + row] = p2;
        }
    }
}

// ---------------- GAT1: 2 rows/block; warp-per-(row,head) softmax; ---------
// float2 aggregation with 8 chains. grid 2048, block 256.
__global__ void k_gat1() {
    __shared__ int   sc[2][MAXD];
    __shared__ float sw[2][HC][MAXD];
    __shared__ float sinv[2][HC];
    int tid = threadIdx.x;
    int row0 = blockIdx.x * 2;
    int rr = tid >> 7, t7 = tid & 127;
    int row = row0 + rr;
    int deg = g_deg[row];
    if (t7 < deg) sc[rr][t7] = g_cols[row * MAXD + t7];
    __syncthreads();
    {   // softmax: warp wid -> (r = wid>>2, g = wid&3); all 8 warps busy
        int wid = tid >> 5, lane = tid & 31;
        int r = wid >> 2, g = wid & 3;
        int srow = row0 + r;
        int d = g_deg[srow];
        float s1i = g_s1h[g * NN + srow];
        float ev[4];
        float m = -1e30f;
#pragma unroll
        for (int jj = 0; jj < 4; jj++) {
            int j = lane + jj * 32;
            ev[jj] = -1e30f;
            if (j < d) {
                float e = s1i + g_s2h[g * NN + sc[r][j]];
                e = e >= 0.f ? e : 0.2f * e;          // leaky_relu(0.2)
                ev[jj] = e;
                m = fmaxf(m, e);
            }
        }
#pragma unroll
        for (int o = 16; o; o >>= 1) m = fmaxf(m, __shfl_xor_sync(0xffffffffu, m, o));
        float s = 0.f;
#pragma unroll
        for (int jj = 0; jj < 4; jj++) {
            int j = lane + jj * 32;
            if (j < d) {
                float w = __expf(ev[jj] - m);
                sw[r][g][j] = w;
                s += w;
            }
        }
#pragma unroll
        for (int o = 16; o; o >>= 1) s += __shfl_xor_sync(0xffffffffu, s, o);
        if (lane == 0) sinv[r][g] = 1.f / s;
    }
    __syncthreads();
    // aggregation: 128 thr/row, thread -> (head g, float2 f2), 8 chains
    int g = t7 >> 5, f2 = (t7 & 31) << 1;
    const float* base = g_WhAll + g * F1C + f2;
    const float* wp = sw[rr][g];
    const int* cp = sc[rr];
    float2 a0 = {0,0}, a1 = {0,0}, a2 = {0,0}, a3 = {0,0};
    float2 a4 = {0,0}, a5 = {0,0}, a6 = {0,0}, a7 = {0,0};
    int j = 0;
    for (; j + 8 <= deg; j += 8) {
        float2 v0 = *(const float2*)(base + (size_t)cp[j + 0] * HF);
        float2 v1 = *(const float2*)(base + (size_t)cp[j + 1] * HF);
        float2 v2 = *(const float2*)(base + (size_t)cp[j + 2] * HF);
        float2 v3 = *(const float2*)(base + (size_t)cp[j + 3] * HF);
        float2 v4 = *(const float2*)(base + (size_t)cp[j + 4] * HF);
        float2 v5 = *(const float2*)(base + (size_t)cp[j + 5] * HF);
        float2 v6 = *(const float2*)(base + (size_t)cp[j + 6] * HF);
        float2 v7 = *(const float2*)(base + (size_t)cp[j + 7] * HF);
        float w0 = wp[j + 0], w1 = wp[j + 1], w2 = wp[j + 2], w3 = wp[j + 3];
        float w4 = wp[j + 4], w5 = wp[j + 5], w6 = wp[j + 6], w7 = wp[j + 7];
        a0.x += w0 * v0.x; a0.y += w0 * v0.y;
        a1.x += w1 * v1.x; a1.y += w1 * v1.y;
        a2.x += w2 * v2.x; a2.y += w2 * v2.y;
        a3.x += w3 * v3.x; a3.y += w3 * v3.y;
        a4.x += w4 * v4.x; a4.y += w4 * v4.y;
        a5.x += w5 * v5.x; a5.y += w5 * v5.y;
        a6.x += w6 * v6.x; a6.y += w6 * v6.y;
        a7.x += w7 * v7.x; a7.y += w7 * v7.y;
    }
    for (; j < deg; j++) {
        float2 v = *(const float2*)(base + (size_t)cp[j] * HF);
        float w = wp[j];
        a0.x += w * v.x; a0.y += w * v.y;
    }
    float inv = sinv[rr][g];
    float ox = (((a0.x + a1.x) + (a2.x + a3.x)) + ((a4.x + a5.x) + (a6.x + a7.x))) * inv;
    float oy = (((a0.y + a1.y) + (a2.y + a3.y)) + ((a4.y + a5.y) + (a6.y + a7.y))) * inv;
    ox = ox > 0.f ? ox : expm1f(ox);                  // ELU
    oy = oy > 0.f ? oy : expm1f(oy);
    *(float2*)(g_cat + (size_t)row * HF + g * F1C + f2) = make_float2(ox, oy);
}

// ---------------- GEMM2: BM=8, 128 thr, register-pipelined chunks ----------
// grid 512. Prefetch chunk c+1 A/B into regs while computing chunk c.
__global__ void k_gemm2(const float* __restrict__ W_att,
                        const float* __restrict__ a_att) {
    __shared__ __align__(16) float sA[32][9];     // [k][row], 8 rows padded
    __shared__ __align__(16) float sB[32][64];
    int bm = blockIdx.x << 3;
    int tid = threadIdx.x;                        // 128 threads
    int row = tid >> 4, cq = (tid & 15) << 2;
    unsigned long long acc2[2] = {};
    // prefetch chunk 0
    float4 ra;                                    // A stage (tid<64)
    float4 rb[4];                                 // B stage
    int ar = tid >> 3, akq = (tid & 7) << 2;      // A: 8 rows x 32k = 64 float4
    if (tid < 64)
        ra = *(const float4*)(g_cat + (size_t)(bm + ar) * HF + akq);
#pragma unroll
    for (int t = 0; t < 4; t++) {
        int idx = tid + t * 128;
        int kr = idx >> 4, bq = (idx & 15) << 2;
        rb[t] = *(const float4*)(W_att + (size_t)kr * F1C + bq);
    }
#pragma unroll
    for (int chunk = 0; chunk < 8; chunk++) {
        // stage regs -> smem
        if (tid < 64) {
            sA[akq + 0][ar] = ra.x; sA[akq + 1][ar] = ra.y;
            sA[akq + 2][ar] = ra.z; sA[akq + 3][ar] = ra.w;
        }
#pragma unroll
        for (int t = 0; t < 4; t++) {
            int idx = tid + t * 128;
            int kr = idx >> 4, bq = (idx & 15) << 2;
            *(float4*)&sB[kr][bq] = rb[t];
        }
        __syncthreads();
        // prefetch next chunk
        if (chunk < 7) {
            int k0 = (chunk + 1) * 32;
            if (tid < 64)
                ra = *(const float4*)(g_cat + (size_t)(bm + ar) * HF + k0 + akq);
#pragma unroll
            for (int t = 0; t < 4; t++) {
                int idx = tid + t * 128;
                int kr = idx >> 4, bq = (idx & 15) << 2;
                rb[t] = *(const float4*)(W_att + (size_t)(k0 + kr) * F1C + bq);
            }
        }
        // compute chunk
#pragma unroll
        for (int kk = 0; kk < 32; kk++) {
            float a = sA[kk][row];
            ulonglong2 bb = *(const ulonglong2*)&sB[kk][cq];
            unsigned long long ap;
            PACK2(ap, __float_as_uint(a), __float_as_uint(a));
            FMA_F32X2(acc2[0], ap, bb.x, acc2[0]);
            FMA_F32X2(acc2[1], ap, bb.y, acc2[1]);
        }
        __syncthreads();
    }
    float4 v = unpack4(*(ulonglong2*)acc2);
    *(float4*)(g_Wh2 + (size_t)(bm + row) * F1C + cq) = v;
    float p1 = v.x * a_att[cq] + v.y * a_att[cq + 1] + v.z * a_att[cq + 2] + v.w * a_att[cq + 3];
    float p2 = v.x * a_att[F1C + cq] + v.y * a_att[F1C + cq + 1]
             + v.z * a_att[F1C + cq + 2] + v.w * a_att[F1C + cq + 3];
#pragma unroll
    for (int o = 8; o; o >>= 1) {
        p1 += __shfl_xor_sync(0xffffffffu, p1, o);
        p2 += __shfl_xor_sync(0xffffffffu, p2, o);
    }
    if ((tid & 15) == 0) {
        g_s1b[bm + row] = p1;
        g_s2b[bm + row] = p2;
    }
}

// ---------------- GAT2 + fc1: 8 rows/block, warp-per-row softmax, ----------
// float2 aggregation (32 thr/row) with 8 chains. grid 512, block 256.
__global__ void k_gat2_fc1(const float* __restrict__ W1) {
    __shared__ int   sc[8][MAXD];
    __shared__ float sw[8][MAXD];
    __shared__ float sinv[8];
    __shared__ float sgc[8][F1C];
    __shared__ float sW1[F1C * F2C];
    int tid = threadIdx.x;
    for (int k = tid; k < F1C * F2C; k += 256) sW1[k] = W1[k];
    int row0 = blockIdx.x * 8;
    {   // cooperative col load: 32 thr per row
        int r = tid >> 5, t = tid & 31;
        int row = row0 + r;
        int d = g_deg[row];
        for (int j = t; j < d; j += 32) sc[r][j] = g_cols[row * MAXD + j];
    }
    __syncthreads();
    int wid = tid >> 5, lane = tid & 31;
    {   // softmax: warp wid -> row wid (all 8 warps busy)
        int row = row0 + wid;
        int d = g_deg[row];
        float s1i = g_s1b[row];
        float ev[4];
        float m = -1e30f;
#pragma unroll
        for (int jj = 0; jj < 4; jj++) {
            int j = lane + jj * 32;
            ev[jj] = -1e30f;
            if (j < d) {
                float e = s1i + g_s2b[sc[wid][j]];
                e = e >= 0.f ? e : 0.2f * e;
                ev[jj] = e;
                m = fmaxf(m, e);
            }
        }
#pragma unroll
        for (int o = 16; o; o >>= 1) m = fmaxf(m, __shfl_xor_sync(0xffffffffu, m, o));
        float s = 0.f;
#pragma unroll
        for (int jj = 0; jj < 4; jj++) {
            int j = lane + jj * 32;
            if (j < d) {
                float w = __expf(ev[jj] - m);
                sw[wid][j] = w;
                s += w;
            }
        }
#pragma unroll
        for (int o = 16; o; o >>= 1) s += __shfl_xor_sync(0xffffffffu, s, o);
        if (lane == 0) sinv[wid] = 1.f / s;
    }
    __syncthreads();
    // aggregation: 32 thr/row, thread -> float2, 8 chains
    int r = wid;
    int row = row0 + r;
    int deg = g_deg[row];
    int f2 = lane << 1;
    const float* base = g_Wh2 + f2;
    const int* cp = sc[r];
    const float* wp = sw[r];
    float2 a0 = {0,0}, a1 = {0,0}, a2 = {0,0}, a3 = {0,0};
    float2 a4 = {0,0}, a5 = {0,0}, a6 = {0,0}, a7 = {0,0};
    int j = 0;
    for (; j + 8 <= deg; j += 8) {
        float2 v0 = *(const float2*)(base + (size_t)cp[j + 0] * F1C);
        float2 v1 = *(const float2*)(base + (size_t)cp[j + 1] * F1C);
        float2 v2 = *(const float2*)(base + (size_t)cp[j + 2] * F1C);
        float2 v3 = *(const float2*)(base + (size_t)cp[j + 3] * F1C);
        float2 v4 = *(const float2*)(base + (size_t)cp[j + 4] * F1C);
        float2 v5 = *(const float2*)(base + (size_t)cp[j + 5] * F1C);
        float2 v6 = *(const float2*)(base + (size_t)cp[j + 6] * F1C);
        float2 v7 = *(const float2*)(base + (size_t)cp[j + 7] * F1C);
        float w0 = wp[j + 0], w1 = wp[j + 1], w2 = wp[j + 2], w3 = wp[j + 3];
        float w4 = wp[j + 4], w5 = wp[j + 5], w6 = wp[j + 6], w7 = wp[j + 7];
        a0.x += w0 * v0.x; a0.y += w0 * v0.y;
        a1.x += w1 * v1.x; a1.y += w1 * v1.y;
        a2.x += w2 * v2.x; a2.y += w2 * v2.y;
        a3.x += w3 * v3.x; a3.y += w3 * v3.y;
        a4.x += w4 * v4.x; a4.y += w4 * v4.y;
        a5.x += w5 * v5.x; a5.y += w5 * v5.y;
        a6.x += w6 * v6.x; a6.y += w6 * v6.y;
        a7.x += w7 * v7.x; a7.y += w7 * v7.y;
    }
    for (; j < deg; j++) {
        float2 v = *(const float2*)(base + (size_t)cp[j] * F1C);
        float w = wp[j];
        a0.x += w * v.x; a0.y += w * v.y;
    }
    float inv = sinv[r];
    float ox = (((a0.x + a1.x) + (a2.x + a3.x)) + ((a4.x + a5.x) + (a6.x + a7.x))) * inv;
    float oy = (((a0.y + a1.y) + (a2.y + a3.y)) + ((a4.y + a5.y) + (a6.y + a7.y))) * inv;
    sgc[r][f2 + 0] = ox > 0.f ? ox : expm1f(ox);     // ELU
    sgc[r][f2 + 1] = oy > 0.f ? oy : expm1f(oy);
    __syncthreads();
    // fc1: 8 rows x 32 outputs = 256 threads, one output each
    int fr = tid >> 5, c = tid & 31;
    float t = 0.f;
#pragma unroll 16
    for (int k = 0; k < F1C; k++) t += sgc[fr][k] * sW1[k * F2C + c];
    g_t1[(row0 + fr) * F2C + c] = t;
}

// ---------------- h1 = relu(adj@t1) fused with t2=h1@W2, t3=h1@W3 ----------
__global__ void k_spmm_fc23(const float* __restrict__ W2,
                            const float* __restrict__ W3) {
    __shared__ float sh[8][F2C];
    __shared__ float w2[F2C * F3C], w3[F2C * F3C];
    int tid = threadIdx.x;                            // 256 threads
    for (int k = tid; k < F2C * F3C; k += 256) { w2[k] = W2[k]; w3[k] = W3[k]; }
    int wid = tid >> 5, lane = tid & 31;
    int row = blockIdx.x * 8 + wid;
    int deg = g_deg[row];
    const int* cp = g_cols + row * MAXD;
    float a0 = 0.f, a1 = 0.f, a2 = 0.f, a3 = 0.f;
    float a4 = 0.f, a5 = 0.f, a6 = 0.f, a7 = 0.f;
    int j = 0;
    for (; j + 8 <= deg; j += 8) {
        a0 += g_t1[cp[j + 0] * F2C + lane];
        a1 += g_t1[cp[j + 1] * F2C + lane];
        a2 += g_t1[cp[j + 2] * F2C + lane];
        a3 += g_t1[cp[j + 3] * F2C + lane];
        a4 += g_t1[cp[j + 4] * F2C + lane];
        a5 += g_t1[cp[j + 5] * F2C + lane];
        a6 += g_t1[cp[j + 6] * F2C + lane];
        a7 += g_t1[cp[j + 7] * F2C + lane];
    }
    for (; j < deg; j++) a0 += g_t1[cp[j] * F2C + lane];
    sh[wid][lane] = fmaxf((((a0 + a1) + (a2 + a3)) + ((a4 + a5) + (a6 + a7))), 0.f);
    __syncthreads();
    int r = tid >> 5, o = tid & 31, f = o & 15;
    const float* w = (o < 16) ? w2 : w3;
    float v = 0.f;
#pragma unroll 8
    for (int k = 0; k < F2C; k++) v += sh[r][k] * w[k * F3C + f];
    float* dst = (o < 16) ? g_t2 : g_t3;
    dst[(blockIdx.x * 8 + r) * F3C + f] = v;
}

// ---------------- mu/logvar spmm + reparameterize --------------------------
__global__ void k_spmm_reparam(const float* __restrict__ eps,
                               float* __restrict__ out_mu,
                               float* __restrict__ out_lv) {
    int tid = threadIdx.x;
    int row = blockIdx.x * 16 + (tid >> 4);
    int f = tid & 15;
    int deg = g_deg[row];
    const int* cp = g_cols + row * MAXD;
    float m0 = 0.f, m1 = 0.f, l0 = 0.f, l1 = 0.f;
    int j = 0;
    for (; j + 2 <= deg; j += 2) {
        int c0 = cp[j], c1 = cp[j + 1];
        m0 += g_t2[c0 * F3C + f];
        l0 += g_t3[c0 * F3C + f];
        m1 += g_t2[c1 * F3C + f];
        l1 += g_t3[c1 * F3C + f];
    }
    if (j < deg) { int c = cp[j]; m0 += g_t2[c * F3C + f]; l0 += g_t3[c * F3C + f]; }
    float mu = m0 + m1, lv = l0 + l1;
    int o = row * F3C + f;
    out_mu[o] = mu;
    out_lv[o] = lv;
    g_z[o] = eps[o] * expf(lv) + mu;
}

// ---------------- adj_rec = z @ z^T (64x64 tile, K=16, write-bound) --------
__global__ void k_zzT(float* __restrict__ out) {
    __shared__ float sa[64][17];
    __shared__ float sb[64][17];
    int bi = blockIdx.y << 6, bj = blockIdx.x << 6;
    int tid = threadIdx.x;
    int r = tid >> 2, q = (tid & 3) << 2;
    float4 va = *(const float4*)(g_z + ((bi + r) << 4) + q);
    sa[r][q + 0] = va.x; sa[r][q + 1] = va.y; sa[r][q + 2] = va.z; sa[r][q + 3] = va.w;
    float4 vb = *(const float4*)(g_z + ((bj + r) << 4) + q);
    sb[r][q + 0] = vb.x; sb[r][q + 1] = vb.y; sb[r][q + 2] = vb.z; sb[r][q + 3] = vb.w;
    __syncthreads();
    int ty = tid >> 4, tx = tid & 15;
    float acc[4][4] = {};
#pragma unroll
    for (int k = 0; k < 16; k++) {
        float a0 = sa[ty * 4 + 0][k], a1 = sa[ty * 4 + 1][k];
        float a2 = sa[ty * 4 + 2][k], a3 = sa[ty * 4 + 3][k];
        float b0 = sb[tx * 4 + 0][k], b1 = sb[tx * 4 + 1][k];
        float b2 = sb[tx * 4 + 2][k], b3 = sb[tx * 4 + 3][k];
        acc[0][0] += a0 * b0; acc[0][1] += a0 * b1; acc[0][2] += a0 * b2; acc[0][3] += a0 * b3;
        acc[1][0] += a1 * b0; acc[1][1] += a1 * b1; acc[1][2] += a1 * b2; acc[1][3] += a1 * b3;
        acc[2][0] += a2 * b0; acc[2][1] += a2 * b1; acc[2][2] += a2 * b2; acc[2][3] += a2 * b3;
        acc[3][0] += a3 * b0; acc[3][1] += a3 * b1; acc[3][2] += a3 * b2; acc[3][3] += a3 * b3;
    }
#pragma unroll
    for (int i = 0; i < 4; i++) {
        float4 v = make_float4(acc[i][0], acc[i][1], acc[i][2], acc[i][3]);
        *(float4*)(out + (size_t)(bi + ty * 4 + i) * NN + bj + (tx << 2)) = v;
    }
}

// ---------------- launch ----------------------------------------------------
extern "C" void kernel_launch(void* const* d_in, const int* in_sizes, int n_in,
                              void* d_out, int out_size) {
    const float* x       = (const float*)d_in[0];
    const float* adj     = (const float*)d_in[1];
    const float* W_heads = (const float*)d_in[2];
    const float* a_heads = (const float*)d_in[3];
    const float* W_att   = (const float*)d_in[4];
    const float* a_att   = (const float*)d_in[5];
    const float* W1      = (const float*)d_in[6];
    const float* W2      = (const float*)d_in[7];
    const float* W3      = (const float*)d_in[8];
    const float* eps     = (const float*)d_in[9];
    float* out = (float*)d_out;
    float* out_mu = out + (size_t)NN * NN;
    float* out_lv = out_mu + (size_t)NN * F3C;

    k_build_gemm1<<<768, 256>>>(adj, x, W_heads, a_heads);  // overlap build + GEMM1
    k_gat1<<<NN / 2, 256>>>();
    k_gemm2<<<NN / 8, 128>>>(W_att, a_att);
    k_gat2_fc1<<<NN / 8, 256>>>(W1);
    k_spmm_fc23<<<NN / 8, 256>>>(W2, W3);
    k_spmm_reparam<<<NN / 16, 256>>>(eps, out_mu, out_lv);
    k_zzT<<<dim3(NN / 64, NN / 64), 256>>>(out);
}

// round 12
// speedup vs baseline: 1.0588x; 1.0588x over previous
#include <cuda_runtime.h>
#include <math.h>

#define NN   4096
#define DD   512
#define F1C  64
#define HC   4
#define HF   256   // HC*F1C
#define F2C  32
#define F3C  16
#define MAXD 128

// packed fp32x2 FMA (Blackwell)
#define FMA_F32X2(d, a, b, c) \
    asm("fma.rn.f32x2 %0, %1, %2, %3;" : "=l"(d) : "l"(a), "l"(b), "l"(c))
#define PACK2(out, lo, hi) \
    asm("mov.b64 %0, {%1, %2};" : "=l"(out) : "r"(lo), "r"(hi))
#define UNPACK2(lo, hi, in) \
    asm("mov.b64 {%0, %1}, %2;" : "=r"(lo), "=r"(hi) : "l"(in))

__device__ __forceinline__ float4 unpack4(ulonglong2 a) {
    unsigned u0, u1, u2, u3;
    UNPACK2(u0, u1, a.x);
    UNPACK2(u2, u3, a.y);
    return make_float4(__uint_as_float(u0), __uint_as_float(u1),
                       __uint_as_float(u2), __uint_as_float(u3));
}

// ---------------- scratch ---------------------------------------------------
__device__ int    g_deg[NN];
__device__ int    g_cols[NN * MAXD];
__device__ float  g_WhAll[NN * HF];      // [i][h*64+f]
__device__ float  g_s1h[HC * NN];        // [head][row]
__device__ float  g_s2h[HC * NN];
__device__ float  g_cat[NN * HF];
__device__ float  g_Wh2[NN * F1C];
__device__ float  g_s1b[NN];
__device__ float  g_s2b[NN];
__device__ float  g_t1[NN * F2C];
__device__ float  g_t2[NN * F3C];
__device__ float  g_t3[NN * F3C];
__device__ float  g_z[NN * F3C];

// ============ fused: blocks [0,256) GEMM1 tiles, [256,768) build ELL ========
__global__ void k_build_gemm1(const float* __restrict__ adj,
                              const float* __restrict__ x,
                              const float* __restrict__ W_heads,
                              const float* __restrict__ a_heads) {
    __shared__ __align__(16) float sA[16][64];
    __shared__ __align__(16) float sB[16][64];
    int bx = blockIdx.x;
    if (bx >= 256) {
        // ---- adjacency build: warp per row; streaming loads (single-use) ---
        int wb = bx - 256;
        int row = wb * 8 + (threadIdx.x >> 5);
        int lane = threadIdx.x & 31;
        const float4* arow = (const float4*)(adj + (size_t)row * NN);
        int cnt = 0;
        for (int j0 = 0; j0 < NN; j0 += 128) {
            float4 v = __ldcs(arow + (j0 >> 2) + lane);
            int base = j0 + lane * 4;
#pragma unroll
            for (int c = 0; c < 4; c++) {
                float val = (c == 0) ? v.x : (c == 1) ? v.y : (c == 2) ? v.z : v.w;
                unsigned m = __ballot_sync(0xffffffffu, val > 0.f);
                if (val > 0.f) {
                    int pos = cnt + __popc(m & ((1u << lane) - 1u));
                    if (pos < MAXD) g_cols[row * MAXD + pos] = base + c;
                }
                cnt += __popc(m);
            }
        }
        if (lane == 0) g_deg[row] = cnt < MAXD ? cnt : MAXD;
        return;
    }
    // ---- GEMM1 tile: head = bx>>6, row-block = bx&63 -----------------------
    int head = bx >> 6;
    int bm = (bx & 63) << 6;
    int tid = threadIdx.x;
    int ty = tid >> 4, tx = tid & 15;
    const float* B = W_heads + (size_t)head * DD * F1C;
    unsigned long long acc2[4][2] = {};
    for (int k0 = 0; k0 < DD; k0 += 16) {
        int ar = tid >> 2, kq = (tid & 3) << 2;
        float4 va = *(const float4*)(x + (size_t)(bm + ar) * DD + k0 + kq);
        sA[kq + 0][ar] = va.x; sA[kq + 1][ar] = va.y;
        sA[kq + 2][ar] = va.z; sA[kq + 3][ar] = va.w;
        int br = tid >> 4, nq = (tid & 15) << 2;
        *(float4*)&sB[br][nq] = *(const float4*)(B + (size_t)(k0 + br) * F1C + nq);
        __syncthreads();
#pragma unroll
        for (int kk = 0; kk < 16; kk++) {
            float4 av = *(const float4*)&sA[kk][ty << 2];
            ulonglong2 bb = *(const ulonglong2*)&sB[kk][tx << 2];
            unsigned long long ap;
            PACK2(ap, __float_as_uint(av.x), __float_as_uint(av.x));
            FMA_F32X2(acc2[0][0], ap, bb.x, acc2[0][0]);
            FMA_F32X2(acc2[0][1], ap, bb.y, acc2[0][1]);
            PACK2(ap, __float_as_uint(av.y), __float_as_uint(av.y));
            FMA_F32X2(acc2[1][0], ap, bb.x, acc2[1][0]);
            FMA_F32X2(acc2[1][1], ap, bb.y, acc2[1][1]);
            PACK2(ap, __float_as_uint(av.z), __float_as_uint(av.z));
            FMA_F32X2(acc2[2][0], ap, bb.x, acc2[2][0]);
            FMA_F32X2(acc2[2][1], ap, bb.y, acc2[2][1]);
            PACK2(ap, __float_as_uint(av.w), __float_as_uint(av.w));
            FMA_F32X2(acc2[3][0], ap, bb.x, acc2[3][0]);
            FMA_F32X2(acc2[3][1], ap, bb.y, acc2[3][1]);
        }
        __syncthreads();
    }
    float acc[4][4];
#pragma unroll
    for (int i = 0; i < 4; i++) {
        float4 t = unpack4(*(ulonglong2*)acc2[i]);
        acc[i][0] = t.x; acc[i][1] = t.y; acc[i][2] = t.z; acc[i][3] = t.w;
    }
#pragma unroll
    for (int i = 0; i < 4; i++) {
        float4 v = make_float4(acc[i][0], acc[i][1], acc[i][2], acc[i][3]);
        *(float4*)(g_WhAll + (size_t)(bm + ty * 4 + i) * HF + head * F1C + (tx << 2)) = v;
    }
    // score epilogue
    const float* ag = a_heads + head * 2 * F1C;
    float a1v[4], a2v[4];
#pragma unroll
    for (int c = 0; c < 4; c++) { a1v[c] = ag[(tx << 2) + c]; a2v[c] = ag[F1C + (tx << 2) + c]; }
#pragma unroll
    for (int i = 0; i < 4; i++) {
        float p1 = acc[i][0] * a1v[0] + acc[i][1] * a1v[1] + acc[i][2] * a1v[2] + acc[i][3] * a1v[3];
        float p2 = acc[i][0] * a2v[0] + acc[i][1] * a2v[1] + acc[i][2] * a2v[2] + acc[i][3] * a2v[3];
#pragma unroll
        for (int o = 8; o; o >>= 1) {
            p1 += __shfl_xor_sync(0xffffffffu, p1, o);
            p2 += __shfl_xor_sync(0xffffffffu, p2, o);
        }
        if (tx == 0) {
            int row = bm + ty * 4 + i;
            g_s1h[head * NN + row] = p1;
            g_s2h[head * NN + row] = p2;
        }
    }
}

// ---------------- GAT1: 2 rows/block; warp-per-(row,head) softmax; ---------
// float2 aggregation with 8 chains. grid 2048, block 256.
__global__ void k_gat1() {
    __shared__ int   sc[2][MAXD];
    __shared__ float sw[2][HC][MAXD];
    __shared__ float sinv[2][HC];
    int tid = threadIdx.x;
    int row0 = blockIdx.x * 2;
    int rr = tid >> 7, t7 = tid & 127;
    int row = row0 + rr;
    int deg = g_deg[row];
    if (t7 < deg) sc[rr][t7] = g_cols[row * MAXD + t7];
    __syncthreads();
    {   // softmax: warp wid -> (r = wid>>2, g = wid&3); all 8 warps busy
        int wid = tid >> 5, lane = tid & 31;
        int r = wid >> 2, g = wid & 3;
        int srow = row0 + r;
        int d = g_deg[srow];
        float s1i = g_s1h[g * NN + srow];
        float ev[4];
        float m = -1e30f;
#pragma unroll
        for (int jj = 0; jj < 4; jj++) {
            int j = lane + jj * 32;
            ev[jj] = -1e30f;
            if (j < d) {
                float e = s1i + g_s2h[g * NN + sc[r][j]];
                e = e >= 0.f ? e : 0.2f * e;          // leaky_relu(0.2)
                ev[jj] = e;
                m = fmaxf(m, e);
            }
        }
#pragma unroll
        for (int o = 16; o; o >>= 1) m = fmaxf(m, __shfl_xor_sync(0xffffffffu, m, o));
        float s = 0.f;
#pragma unroll
        for (int jj = 0; jj < 4; jj++) {
            int j = lane + jj * 32;
            if (j < d) {
                float w = __expf(ev[jj] - m);
                sw[r][g][j] = w;
                s += w;
            }
        }
#pragma unroll
        for (int o = 16; o; o >>= 1) s += __shfl_xor_sync(0xffffffffu, s, o);
        if (lane == 0) sinv[r][g] = 1.f / s;
    }
    __syncthreads();
    // aggregation: 128 thr/row, thread -> (head g, float2 f2), 8 chains
    int g = t7 >> 5, f2 = (t7 & 31) << 1;
    const float* base = g_WhAll + g * F1C + f2;
    const float* wp = sw[rr][g];
    const int* cp = sc[rr];
    float2 a0 = {0,0}, a1 = {0,0}, a2 = {0,0}, a3 = {0,0};
    float2 a4 = {0,0}, a5 = {0,0}, a6 = {0,0}, a7 = {0,0};
    int j = 0;
    for (; j + 8 <= deg; j += 8) {
        float2 v0 = *(const float2*)(base + (size_t)cp[j + 0] * HF);
        float2 v1 = *(const float2*)(base + (size_t)cp[j + 1] * HF);
        float2 v2 = *(const float2*)(base + (size_t)cp[j + 2] * HF);
        float2 v3 = *(const float2*)(base + (size_t)cp[j + 3] * HF);
        float2 v4 = *(const float2*)(base + (size_t)cp[j + 4] * HF);
        float2 v5 = *(const float2*)(base + (size_t)cp[j + 5] * HF);
        float2 v6 = *(const float2*)(base + (size_t)cp[j + 6] * HF);
        float2 v7 = *(const float2*)(base + (size_t)cp[j + 7] * HF);
        float w0 = wp[j + 0], w1 = wp[j + 1], w2 = wp[j + 2], w3 = wp[j + 3];
        float w4 = wp[j + 4], w5 = wp[j + 5], w6 = wp[j + 6], w7 = wp[j + 7];
        a0.x += w0 * v0.x; a0.y += w0 * v0.y;
        a1.x += w1 * v1.x; a1.y += w1 * v1.y;
        a2.x += w2 * v2.x; a2.y += w2 * v2.y;
        a3.x += w3 * v3.x; a3.y += w3 * v3.y;
        a4.x += w4 * v4.x; a4.y += w4 * v4.y;
        a5.x += w5 * v5.x; a5.y += w5 * v5.y;
        a6.x += w6 * v6.x; a6.y += w6 * v6.y;
        a7.x += w7 * v7.x; a7.y += w7 * v7.y;
    }
    for (; j < deg; j++) {
        float2 v = *(const float2*)(base + (size_t)cp[j] * HF);
        float w = wp[j];
        a0.x += w * v.x; a0.y += w * v.y;
    }
    float inv = sinv[rr][g];
    float ox = (((a0.x + a1.x) + (a2.x + a3.x)) + ((a4.x + a5.x) + (a6.x + a7.x))) * inv;
    float oy = (((a0.y + a1.y) + (a2.y + a3.y)) + ((a4.y + a5.y) + (a6.y + a7.y))) * inv;
    ox = ox > 0.f ? ox : expm1f(ox);                  // ELU
    oy = oy > 0.f ? oy : expm1f(oy);
    *(float2*)(g_cat + (size_t)row * HF + g * F1C + f2) = make_float2(ox, oy);
}

// ---------------- GEMM2: BM=8, 128 thr, register-pipelined chunks ----------
// grid 512. Prefetch chunk c+1 A/B into regs while computing chunk c.
__global__ void k_gemm2(const float* __restrict__ W_att,
                        const float* __restrict__ a_att) {
    __shared__ __align__(16) float sA[32][9];     // [k][row], 8 rows padded
    __shared__ __align__(16) float sB[32][64];
    int bm = blockIdx.x << 3;
    int tid = threadIdx.x;                        // 128 threads
    int row = tid >> 4, cq = (tid & 15) << 2;
    unsigned long long acc2[2] = {};
    // prefetch chunk 0
    float4 ra;                                    // A stage (tid<64)
    float4 rb[4];                                 // B stage
    int ar = tid >> 3, akq = (tid & 7) << 2;      // A: 8 rows x 32k = 64 float4
    if (tid < 64)
        ra = *(const float4*)(g_cat + (size_t)(bm + ar) * HF + akq);
#pragma unroll
    for (int t = 0; t < 4; t++) {
        int idx = tid + t * 128;
        int kr = idx >> 4, bq = (idx & 15) << 2;
        rb[t] = *(const float4*)(W_att + (size_t)kr * F1C + bq);
    }
#pragma unroll
    for (int chunk = 0; chunk < 8; chunk++) {
        // stage regs -> smem
        if (tid < 64) {
            sA[akq + 0][ar] = ra.x; sA[akq + 1][ar] = ra.y;
            sA[akq + 2][ar] = ra.z; sA[akq + 3][ar] = ra.w;
        }
#pragma unroll
        for (int t = 0; t < 4; t++) {
            int idx = tid + t * 128;
            int kr = idx >> 4, bq = (idx & 15) << 2;
            *(float4*)&sB[kr][bq] = rb[t];
        }
        __syncthreads();
        // prefetch next chunk
        if (chunk < 7) {
            int k0 = (chunk + 1) * 32;
            if (tid < 64)
                ra = *(const float4*)(g_cat + (size_t)(bm + ar) * HF + k0 + akq);
#pragma unroll
            for (int t = 0; t < 4; t++) {
                int idx = tid + t * 128;
                int kr = idx >> 4, bq = (idx & 15) << 2;
                rb[t] = *(const float4*)(W_att + (size_t)(k0 + kr) * F1C + bq);
            }
        }
        // compute chunk
#pragma unroll
        for (int kk = 0; kk < 32; kk++) {
            float a = sA[kk][row];
            ulonglong2 bb = *(const ulonglong2*)&sB[kk][cq];
            unsigned long long ap;
            PACK2(ap, __float_as_uint(a), __float_as_uint(a));
            FMA_F32X2(acc2[0], ap, bb.x, acc2[0]);
            FMA_F32X2(acc2[1], ap, bb.y, acc2[1]);
        }
        __syncthreads();
    }
    float4 v = unpack4(*(ulonglong2*)acc2);
    *(float4*)(g_Wh2 + (size_t)(bm + row) * F1C + cq) = v;
    float p1 = v.x * a_att[cq] + v.y * a_att[cq + 1] + v.z * a_att[cq + 2] + v.w * a_att[cq + 3];
    float p2 = v.x * a_att[F1C + cq] + v.y * a_att[F1C + cq + 1]
             + v.z * a_att[F1C + cq + 2] + v.w * a_att[F1C + cq + 3];
#pragma unroll
    for (int o = 8; o; o >>= 1) {
        p1 += __shfl_xor_sync(0xffffffffu, p1, o);
        p2 += __shfl_xor_sync(0xffffffffu, p2, o);
    }
    if ((tid & 15) == 0) {
        g_s1b[bm + row] = p1;
        g_s2b[bm + row] = p2;
    }
}

// ---------------- GAT2 + fc1: 4 rows per block (256 thr), warp softmax -----
// (R10 configuration: 5KB smem, high occupancy — measured best at 13.1us)
__global__ void k_gat2_fc1(const float* __restrict__ W1) {
    __shared__ int   sc[4][MAXD];
    __shared__ float sw[4][MAXD];
    __shared__ float sinv[4];
    __shared__ float sgc[4][F1C];
    int tid = threadIdx.x;
    int grp = tid >> 6, gt = tid & 63;        // 4 groups of 64 threads
    int row = blockIdx.x * 4 + grp;
    int deg = g_deg[row];
    for (int j = gt; j < deg; j += 64) sc[grp][j] = g_cols[row * MAXD + j];
    __syncthreads();
    if (gt < 32) {                             // warp 2*grp does softmax
        int lane = gt;
        float s1i = g_s1b[row];
        float m = -1e30f;
        for (int j = lane; j < deg; j += 32) {
            float e = s1i + g_s2b[sc[grp][j]];
            e = e >= 0.f ? e : 0.2f * e;
            sw[grp][j] = e;
            m = fmaxf(m, e);
        }
#pragma unroll
        for (int o = 16; o; o >>= 1) m = fmaxf(m, __shfl_xor_sync(0xffffffffu, m, o));
        float s = 0.f;
        for (int j = lane; j < deg; j += 32) {
            float w = __expf(sw[grp][j] - m);
            sw[grp][j] = w;
            s += w;
        }
#pragma unroll
        for (int o = 16; o; o >>= 1) s += __shfl_xor_sync(0xffffffffu, s, o);
        if (lane == 0) sinv[grp] = 1.f / s;
    }
    __syncthreads();
    const float* base = g_Wh2 + gt;
    const int* cp = sc[grp];
    const float* wp = sw[grp];
    float a0 = 0.f, a1 = 0.f, a2 = 0.f, a3 = 0.f;
    float a4 = 0.f, a5 = 0.f, a6 = 0.f, a7 = 0.f;
    int j = 0;
    for (; j + 8 <= deg; j += 8) {
        a0 += wp[j + 0] * base[(size_t)cp[j + 0] * F1C];
        a1 += wp[j + 1] * base[(size_t)cp[j + 1] * F1C];
        a2 += wp[j + 2] * base[(size_t)cp[j + 2] * F1C];
        a3 += wp[j + 3] * base[(size_t)cp[j + 3] * F1C];
        a4 += wp[j + 4] * base[(size_t)cp[j + 4] * F1C];
        a5 += wp[j + 5] * base[(size_t)cp[j + 5] * F1C];
        a6 += wp[j + 6] * base[(size_t)cp[j + 6] * F1C];
        a7 += wp[j + 7] * base[(size_t)cp[j + 7] * F1C];
    }
    for (; j < deg; j++) a0 += wp[j] * base[(size_t)cp[j] * F1C];
    float acc = (((a0 + a1) + (a2 + a3)) + ((a4 + a5) + (a6 + a7))) * sinv[grp];
    sgc[grp][gt] = acc > 0.f ? acc : expm1f(acc);   // ELU
    __syncthreads();
    if (gt < F2C) {
        float t = 0.f;
#pragma unroll 16
        for (int k = 0; k < F1C; k++) t += sgc[grp][k] * W1[k * F2C + gt];
        g_t1[row * F2C + gt] = t;
    }
}

// ---------------- h1 = relu(adj@t1) fused with t2=h1@W2, t3=h1@W3 ----------
__global__ void k_spmm_fc23(const float* __restrict__ W2,
                            const float* __restrict__ W3) {
    __shared__ float sh[8][F2C];
    __shared__ float w2[F2C * F3C], w3[F2C * F3C];
    int tid = threadIdx.x;                            // 256 threads
    for (int k = tid; k < F2C * F3C; k += 256) { w2[k] = W2[k]; w3[k] = W3[k]; }
    int wid = tid >> 5, lane = tid & 31;
    int row = blockIdx.x * 8 + wid;
    int deg = g_deg[row];
    const int* cp = g_cols + row * MAXD;
    float a0 = 0.f, a1 = 0.f, a2 = 0.f, a3 = 0.f;
    float a4 = 0.f, a5 = 0.f, a6 = 0.f, a7 = 0.f;
    int j = 0;
    for (; j + 8 <= deg; j += 8) {
        a0 += g_t1[cp[j + 0] * F2C + lane];
        a1 += g_t1[cp[j + 1] * F2C + lane];
        a2 += g_t1[cp[j + 2] * F2C + lane];
        a3 += g_t1[cp[j + 3] * F2C + lane];
        a4 += g_t1[cp[j + 4] * F2C + lane];
        a5 += g_t1[cp[j + 5] * F2C + lane];
        a6 += g_t1[cp[j + 6] * F2C + lane];
        a7 += g_t1[cp[j + 7] * F2C + lane];
    }
    for (; j < deg; j++) a0 += g_t1[cp[j] * F2C + lane];
    sh[wid][lane] = fmaxf((((a0 + a1) + (a2 + a3)) + ((a4 + a5) + (a6 + a7))), 0.f);
    __syncthreads();
    int r = tid >> 5, o = tid & 31, f = o & 15;
    const float* w = (o < 16) ? w2 : w3;
    float v = 0.f;
#pragma unroll 8
    for (int k = 0; k < F2C; k++) v += sh[r][k] * w[k * F3C + f];
    float* dst = (o < 16) ? g_t2 : g_t3;
    dst[(blockIdx.x * 8 + r) * F3C + f] = v;
}

// ---------------- mu/logvar spmm + reparameterize --------------------------
__global__ void k_spmm_reparam(const float* __restrict__ eps,
                               float* __restrict__ out_mu,
                               float* __restrict__ out_lv) {
    int tid = threadIdx.x;
    int row = blockIdx.x * 16 + (tid >> 4);
    int f = tid & 15;
    int deg = g_deg[row];
    const int* cp = g_cols + row * MAXD;
    float m0 = 0.f, m1 = 0.f, l0 = 0.f, l1 = 0.f;
    int j = 0;
    for (; j + 2 <= deg; j += 2) {
        int c0 = cp[j], c1 = cp[j + 1];
        m0 += g_t2[c0 * F3C + f];
        l0 += g_t3[c0 * F3C + f];
        m1 += g_t2[c1 * F3C + f];
        l1 += g_t3[c1 * F3C + f];
    }
    if (j < deg) { int c = cp[j]; m0 += g_t2[c * F3C + f]; l0 += g_t3[c * F3C + f]; }
    float mu = m0 + m1, lv = l0 + l1;
    int o = row * F3C + f;
    out_mu[o] = mu;
    out_lv[o] = lv;
    g_z[o] = eps[o] * expf(lv) + mu;
}

// ---------------- adj_rec = z @ z^T (64x64 tile, K=16, write-bound) --------
__global__ void k_zzT(float* __restrict__ out) {
    __shared__ float sa[64][17];
    __shared__ float sb[64][17];
    int bi = blockIdx.y << 6, bj = blockIdx.x << 6;
    int tid = threadIdx.x;
    int r = tid >> 2, q = (tid & 3) << 2;
    float4 va = *(const float4*)(g_z + ((bi + r) << 4) + q);
    sa[r][q + 0] = va.x; sa[r][q + 1] = va.y; sa[r][q + 2] = va.z; sa[r][q + 3] = va.w;
    float4 vb = *(const float4*)(g_z + ((bj + r) << 4) + q);
    sb[r][q + 0] = vb.x; sb[r][q + 1] = vb.y; sb[r][q + 2] = vb.z; sb[r][q + 3] = vb.w;
    __syncthreads();
    int ty = tid >> 4, tx = tid & 15;
    float acc[4][4] = {};
#pragma unroll
    for (int k = 0; k < 16; k++) {
        float a0 = sa[ty * 4 + 0][k], a1 = sa[ty * 4 + 1][k];
        float a2 = sa[ty * 4 + 2][k], a3 = sa[ty * 4 + 3][k];
        float b0 = sb[tx * 4 + 0][k], b1 = sb[tx * 4 + 1][k];
        float b2 = sb[tx * 4 + 2][k], b3 = sb[tx * 4 + 3][k];
        acc[0][0] += a0 * b0; acc[0][1] += a0 * b1; acc[0][2] += a0 * b2; acc[0][3] += a0 * b3;
        acc[1][0] += a1 * b0; acc[1][1] += a1 * b1; acc[1][2] += a1 * b2; acc[1][3] += a1 * b3;
        acc[2][0] += a2 * b0; acc[2][1] += a2 * b1; acc[2][2] += a2 * b2; acc[2][3] += a2 * b3;
        acc[3][0] += a3 * b0; acc[3][1] += a3 * b1; acc[3][2] += a3 * b2; acc[3][3] += a3 * b3;
    }
#pragma unroll
    for (int i = 0; i < 4; i++) {
        float4 v = make_float4(acc[i][0], acc[i][1], acc[i][2], acc[i][3]);
        __stcs((float4*)(out + (size_t)(bi + ty * 4 + i) * NN + bj + (tx << 2)), v);
    }
}

// ---------------- launch ----------------------------------------------------
extern "C" void kernel_launch(void* const* d_in, const int* in_sizes, int n_in,
                              void* d_out, int out_size) {
    const float* x       = (const float*)d_in[0];
    const float* adj     = (const float*)d_in[1];
    const float* W_heads = (const float*)d_in[2];
    const float* a_heads = (const float*)d_in[3];
    const float* W_att   = (const float*)d_in[4];
    const float* a_att   = (const float*)d_in[5];
    const float* W1      = (const float*)d_in[6];
    const float* W2      = (const float*)d_in[7];
    const float* W3      = (const float*)d_in[8];
    const float* eps     = (const float*)d_in[9];
    float* out = (float*)d_out;
    float* out_mu = out + (size_t)NN * NN;
    float* out_lv = out_mu + (size_t)NN * F3C;

    k_build_gemm1<<<768, 256>>>(adj, x, W_heads, a_heads);  // overlap build + GEMM1
    k_gat1<<<NN / 2, 256>>>();
    k_gemm2<<<NN / 8, 128>>>(W_att, a_att);
    k_gat2_fc1<<<NN / 4, 256>>>(W1);
    k_spmm_fc23<<<NN / 8, 256>>>(W2, W3);
    k_spmm_reparam<<<NN / 16, 256>>>(eps, out_mu, out_lv);
    k_zzT<<<dim3(NN / 64, NN / 64), 256>>>(out);
}

// round 13
// speedup vs baseline: 1.1021x; 1.0409x over previous
#include <cuda_runtime.h>
#include <math.h>

#define NN   4096
#define DD   512
#define F1C  64
#define HC   4
#define HF   256   // HC*F1C
#define F2C  32
#define F3C  16
#define MAXD 128

// packed fp32x2 FMA (Blackwell)
#define FMA_F32X2(d, a, b, c) \
    asm("fma.rn.f32x2 %0, %1, %2, %3;" : "=l"(d) : "l"(a), "l"(b), "l"(c))
#define PACK2(out, lo, hi) \
    asm("mov.b64 %0, {%1, %2};" : "=l"(out) : "r"(lo), "r"(hi))
#define UNPACK2(lo, hi, in) \
    asm("mov.b64 {%0, %1}, %2;" : "=r"(lo), "=r"(hi) : "l"(in))

__device__ __forceinline__ float4 unpack4(ulonglong2 a) {
    unsigned u0, u1, u2, u3;
    UNPACK2(u0, u1, a.x);
    UNPACK2(u2, u3, a.y);
    return make_float4(__uint_as_float(u0), __uint_as_float(u1),
                       __uint_as_float(u2), __uint_as_float(u3));
}

// ---------------- scratch ---------------------------------------------------
__device__ int    g_deg[NN];
__device__ int    g_cols[NN * MAXD];
__device__ float  g_WhAll[NN * HF];      // [i][h*64+f]
__device__ float  g_s1h[HC * NN];        // [head][row]
__device__ float  g_s2h[HC * NN];
__device__ float  g_cat[NN * HF];
__device__ float  g_Wh2[NN * F1C];
__device__ float  g_s1b[NN];
__device__ float  g_s2b[NN];
__device__ float  g_t1[NN * F2C];
__device__ float  g_t2[NN * F3C];
__device__ float  g_t3[NN * F3C];
__device__ float  g_z[NN * F3C];

// ============ fused: blocks [0,256) GEMM1 tiles, [256,768) build ELL ========
__global__ void k_build_gemm1(const float* __restrict__ adj,
                              const float* __restrict__ x,
                              const float* __restrict__ W_heads,
                              const float* __restrict__ a_heads) {
    __shared__ __align__(16) float sA[16][64];
    __shared__ __align__(16) float sB[16][64];
    int bx = blockIdx.x;
    if (bx >= 256) {
        // ---- adjacency build: warp per row; streaming loads (single-use) ---
        int wb = bx - 256;
        int row = wb * 8 + (threadIdx.x >> 5);
        int lane = threadIdx.x & 31;
        const float4* arow = (const float4*)(adj + (size_t)row * NN);
        int cnt = 0;
        for (int j0 = 0; j0 < NN; j0 += 128) {
            float4 v = __ldcs(arow + (j0 >> 2) + lane);
            int base = j0 + lane * 4;
#pragma unroll
            for (int c = 0; c < 4; c++) {
                float val = (c == 0) ? v.x : (c == 1) ? v.y : (c == 2) ? v.z : v.w;
                unsigned m = __ballot_sync(0xffffffffu, val > 0.f);
                if (val > 0.f) {
                    int pos = cnt + __popc(m & ((1u << lane) - 1u));
                    if (pos < MAXD) g_cols[row * MAXD + pos] = base + c;
                }
                cnt += __popc(m);
            }
        }
        if (lane == 0) g_deg[row] = cnt < MAXD ? cnt : MAXD;
        return;
    }
    // ---- GEMM1 tile: head = bx>>6, row-block = bx&63 -----------------------
    int head = bx >> 6;
    int bm = (bx & 63) << 6;
    int tid = threadIdx.x;
    int ty = tid >> 4, tx = tid & 15;
    const float* B = W_heads + (size_t)head * DD * F1C;
    unsigned long long acc2[4][2] = {};
    for (int k0 = 0; k0 < DD; k0 += 16) {
        int ar = tid >> 2, kq = (tid & 3) << 2;
        float4 va = *(const float4*)(x + (size_t)(bm + ar) * DD + k0 + kq);
        sA[kq + 0][ar] = va.x; sA[kq + 1][ar] = va.y;
        sA[kq + 2][ar] = va.z; sA[kq + 3][ar] = va.w;
        int br = tid >> 4, nq = (tid & 15) << 2;
        *(float4*)&sB[br][nq] = *(const float4*)(B + (size_t)(k0 + br) * F1C + nq);
        __syncthreads();
#pragma unroll
        for (int kk = 0; kk < 16; kk++) {
            float4 av = *(const float4*)&sA[kk][ty << 2];
            ulonglong2 bb = *(const ulonglong2*)&sB[kk][tx << 2];
            unsigned long long ap;
            PACK2(ap, __float_as_uint(av.x), __float_as_uint(av.x));
            FMA_F32X2(acc2[0][0], ap, bb.x, acc2[0][0]);
            FMA_F32X2(acc2[0][1], ap, bb.y, acc2[0][1]);
            PACK2(ap, __float_as_uint(av.y), __float_as_uint(av.y));
            FMA_F32X2(acc2[1][0], ap, bb.x, acc2[1][0]);
            FMA_F32X2(acc2[1][1], ap, bb.y, acc2[1][1]);
            PACK2(ap, __float_as_uint(av.z), __float_as_uint(av.z));
            FMA_F32X2(acc2[2][0], ap, bb.x, acc2[2][0]);
            FMA_F32X2(acc2[2][1], ap, bb.y, acc2[2][1]);
            PACK2(ap, __float_as_uint(av.w), __float_as_uint(av.w));
            FMA_F32X2(acc2[3][0], ap, bb.x, acc2[3][0]);
            FMA_F32X2(acc2[3][1], ap, bb.y, acc2[3][1]);
        }
        __syncthreads();
    }
    float acc[4][4];
#pragma unroll
    for (int i = 0; i < 4; i++) {
        float4 t = unpack4(*(ulonglong2*)acc2[i]);
        acc[i][0] = t.x; acc[i][1] = t.y; acc[i][2] = t.z; acc[i][3] = t.w;
    }
#pragma unroll
    for (int i = 0; i < 4; i++) {
        float4 v = make_float4(acc[i][0], acc[i][1], acc[i][2], acc[i][3]);
        *(float4*)(g_WhAll + (size_t)(bm + ty * 4 + i) * HF + head * F1C + (tx << 2)) = v;
    }
    // score epilogue
    const float* ag = a_heads + head * 2 * F1C;
    float a1v[4], a2v[4];
#pragma unroll
    for (int c = 0; c < 4; c++) { a1v[c] = ag[(tx << 2) + c]; a2v[c] = ag[F1C + (tx << 2) + c]; }
#pragma unroll
    for (int i = 0; i < 4; i++) {
        float p1 = acc[i][0] * a1v[0] + acc[i][1] * a1v[1] + acc[i][2] * a1v[2] + acc[i][3] * a1v[3];
        float p2 = acc[i][0] * a2v[0] + acc[i][1] * a2v[1] + acc[i][2] * a2v[2] + acc[i][3] * a2v[3];
#pragma unroll
        for (int o = 8; o; o >>= 1) {
            p1 += __shfl_xor_sync(0xffffffffu, p1, o);
            p2 += __shfl_xor_sync(0xffffffffu, p2, o);
        }
        if (tx == 0) {
            int row = bm + ty * 4 + i;
            g_s1h[head * NN + row] = p1;
            g_s2h[head * NN + row] = p2;
        }
    }
}

// ---------------- GAT1: 2 rows/block; warp-per-(row,head) softmax; ---------
// float2 aggregation with 8 chains. grid 2048, block 256.
__global__ void k_gat1() {
    __shared__ int   sc[2][MAXD];
    __shared__ float sw[2][HC][MAXD];
    __shared__ float sinv[2][HC];
    int tid = threadIdx.x;
    int row0 = blockIdx.x * 2;
    int rr = tid >> 7, t7 = tid & 127;
    int row = row0 + rr;
    int deg = g_deg[row];
    if (t7 < deg) sc[rr][t7] = g_cols[row * MAXD + t7];
    __syncthreads();
    {   // softmax: warp wid -> (r = wid>>2, g = wid&3); all 8 warps busy
        int wid = tid >> 5, lane = tid & 31;
        int r = wid >> 2, g = wid & 3;
        int srow = row0 + r;
        int d = g_deg[srow];
        float s1i = g_s1h[g * NN + srow];
        float ev[4];
        float m = -1e30f;
#pragma unroll
        for (int jj = 0; jj < 4; jj++) {
            int j = lane + jj * 32;
            ev[jj] = -1e30f;
            if (j < d) {
                float e = s1i + g_s2h[g * NN + sc[r][j]];
                e = e >= 0.f ? e : 0.2f * e;          // leaky_relu(0.2)
                ev[jj] = e;
                m = fmaxf(m, e);
            }
        }
#pragma unroll
        for (int o = 16; o; o >>= 1) m = fmaxf(m, __shfl_xor_sync(0xffffffffu, m, o));
        float s = 0.f;
#pragma unroll
        for (int jj = 0; jj < 4; jj++) {
            int j = lane + jj * 32;
            if (j < d) {
                float w = __expf(ev[jj] - m);
                sw[r][g][j] = w;
                s += w;
            }
        }
#pragma unroll
        for (int o = 16; o; o >>= 1) s += __shfl_xor_sync(0xffffffffu, s, o);
        if (lane == 0) sinv[r][g] = 1.f / s;
    }
    __syncthreads();
    // aggregation: 128 thr/row, thread -> (head g, float2 f2), 8 chains
    int g = t7 >> 5, f2 = (t7 & 31) << 1;
    const float* base = g_WhAll + g * F1C + f2;
    const float* wp = sw[rr][g];
    const int* cp = sc[rr];
    float2 a0 = {0,0}, a1 = {0,0}, a2 = {0,0}, a3 = {0,0};
    float2 a4 = {0,0}, a5 = {0,0}, a6 = {0,0}, a7 = {0,0};
    int j = 0;
    for (; j + 8 <= deg; j += 8) {
        float2 v0 = *(const float2*)(base + (size_t)cp[j + 0] * HF);
        float2 v1 = *(const float2*)(base + (size_t)cp[j + 1] * HF);
        float2 v2 = *(const float2*)(base + (size_t)cp[j + 2] * HF);
        float2 v3 = *(const float2*)(base + (size_t)cp[j + 3] * HF);
        float2 v4 = *(const float2*)(base + (size_t)cp[j + 4] * HF);
        float2 v5 = *(const float2*)(base + (size_t)cp[j + 5] * HF);
        float2 v6 = *(const float2*)(base + (size_t)cp[j + 6] * HF);
        float2 v7 = *(const float2*)(base + (size_t)cp[j + 7] * HF);
        float w0 = wp[j + 0], w1 = wp[j + 1], w2 = wp[j + 2], w3 = wp[j + 3];
        float w4 = wp[j + 4], w5 = wp[j + 5], w6 = wp[j + 6], w7 = wp[j + 7];
        a0.x += w0 * v0.x; a0.y += w0 * v0.y;
        a1.x += w1 * v1.x; a1.y += w1 * v1.y;
        a2.x += w2 * v2.x; a2.y += w2 * v2.y;
        a3.x += w3 * v3.x; a3.y += w3 * v3.y;
        a4.x += w4 * v4.x; a4.y += w4 * v4.y;
        a5.x += w5 * v5.x; a5.y += w5 * v5.y;
        a6.x += w6 * v6.x; a6.y += w6 * v6.y;
        a7.x += w7 * v7.x; a7.y += w7 * v7.y;
    }
    for (; j < deg; j++) {
        float2 v = *(const float2*)(base + (size_t)cp[j] * HF);
        float w = wp[j];
        a0.x += w * v.x; a0.y += w * v.y;
    }
    float inv = sinv[rr][g];
    float ox = (((a0.x + a1.x) + (a2.x + a3.x)) + ((a4.x + a5.x) + (a6.x + a7.x))) * inv;
    float oy = (((a0.y + a1.y) + (a2.y + a3.y)) + ((a4.y + a5.y) + (a6.y + a7.y))) * inv;
    ox = ox > 0.f ? ox : expm1f(ox);                  // ELU
    oy = oy > 0.f ? oy : expm1f(oy);
    *(float2*)(g_cat + (size_t)row * HF + g * F1C + f2) = make_float2(ox, oy);
}

// ---------------- GEMM2: BM=8, 128 thr, register-pipelined chunks ----------
// grid 512. Prefetch chunk c+1 A/B into regs while computing chunk c.
__global__ void k_gemm2(const float* __restrict__ W_att,
                        const float* __restrict__ a_att) {
    __shared__ __align__(16) float sA[32][9];     // [k][row], 8 rows padded
    __shared__ __align__(16) float sB[32][64];
    int bm = blockIdx.x << 3;
    int tid = threadIdx.x;                        // 128 threads
    int row = tid >> 4, cq = (tid & 15) << 2;
    unsigned long long acc2[2] = {};
    // prefetch chunk 0
    float4 ra;                                    // A stage (tid<64)
    float4 rb[4];                                 // B stage
    int ar = tid >> 3, akq = (tid & 7) << 2;      // A: 8 rows x 32k = 64 float4
    if (tid < 64)
        ra = *(const float4*)(g_cat + (size_t)(bm + ar) * HF + akq);
#pragma unroll
    for (int t = 0; t < 4; t++) {
        int idx = tid + t * 128;
        int kr = idx >> 4, bq = (idx & 15) << 2;
        rb[t] = *(const float4*)(W_att + (size_t)kr * F1C + bq);
    }
#pragma unroll
    for (int chunk = 0; chunk < 8; chunk++) {
        // stage regs -> smem
        if (tid < 64) {
            sA[akq + 0][ar] = ra.x; sA[akq + 1][ar] = ra.y;
            sA[akq + 2][ar] = ra.z; sA[akq + 3][ar] = ra.w;
        }
#pragma unroll
        for (int t = 0; t < 4; t++) {
            int idx = tid + t * 128;
            int kr = idx >> 4, bq = (idx & 15) << 2;
            *(float4*)&sB[kr][bq] = rb[t];
        }
        __syncthreads();
        // prefetch next chunk
        if (chunk < 7) {
            int k0 = (chunk + 1) * 32;
            if (tid < 64)
                ra = *(const float4*)(g_cat + (size_t)(bm + ar) * HF + k0 + akq);
#pragma unroll
            for (int t = 0; t < 4; t++) {
                int idx = tid + t * 128;
                int kr = idx >> 4, bq = (idx & 15) << 2;
                rb[t] = *(const float4*)(W_att + (size_t)(k0 + kr) * F1C + bq);
            }
        }
        // compute chunk
#pragma unroll
        for (int kk = 0; kk < 32; kk++) {
            float a = sA[kk][row];
            ulonglong2 bb = *(const ulonglong2*)&sB[kk][cq];
            unsigned long long ap;
            PACK2(ap, __float_as_uint(a), __float_as_uint(a));
            FMA_F32X2(acc2[0], ap, bb.x, acc2[0]);
            FMA_F32X2(acc2[1], ap, bb.y, acc2[1]);
        }
        __syncthreads();
    }
    float4 v = unpack4(*(ulonglong2*)acc2);
    *(float4*)(g_Wh2 + (size_t)(bm + row) * F1C + cq) = v;
    float p1 = v.x * a_att[cq] + v.y * a_att[cq + 1] + v.z * a_att[cq + 2] + v.w * a_att[cq + 3];
    float p2 = v.x * a_att[F1C + cq] + v.y * a_att[F1C + cq + 1]
             + v.z * a_att[F1C + cq + 2] + v.w * a_att[F1C + cq + 3];
#pragma unroll
    for (int o = 8; o; o >>= 1) {
        p1 += __shfl_xor_sync(0xffffffffu, p1, o);
        p2 += __shfl_xor_sync(0xffffffffu, p2, o);
    }
    if ((tid & 15) == 0) {
        g_s1b[bm + row] = p1;
        g_s2b[bm + row] = p2;
    }
}

// ---------------- GAT2 + fc1: warp-autonomous (warp per row, no BAR) -------
// grid 1024, block 128 (4 independent warps). float2 aggregation, 8 chains.
__global__ void k_gat2_fc1(const float* __restrict__ W1) {
    __shared__ int   sc[4][MAXD];
    __shared__ float sw[4][MAXD];
    __shared__ float sgc[4][F1C];
    int tid = threadIdx.x;
    int grp = tid >> 5, lane = tid & 31;
    int row = blockIdx.x * 4 + grp;
    int deg = g_deg[row];
    for (int j = lane; j < deg; j += 32) sc[grp][j] = g_cols[row * MAXD + j];
    __syncwarp();
    // softmax (this warp's row only)
    float s1i = g_s1b[row];
    float ev[4];
    float m = -1e30f;
#pragma unroll
    for (int jj = 0; jj < 4; jj++) {
        int j = lane + jj * 32;
        ev[jj] = -1e30f;
        if (j < deg) {
            float e = s1i + g_s2b[sc[grp][j]];
            e = e >= 0.f ? e : 0.2f * e;
            ev[jj] = e;
            m = fmaxf(m, e);
        }
    }
#pragma unroll
    for (int o = 16; o; o >>= 1) m = fmaxf(m, __shfl_xor_sync(0xffffffffu, m, o));
    float s = 0.f;
#pragma unroll
    for (int jj = 0; jj < 4; jj++) {
        int j = lane + jj * 32;
        if (j < deg) {
            float w = __expf(ev[jj] - m);
            sw[grp][j] = w;
            s += w;
        }
    }
#pragma unroll
    for (int o = 16; o; o >>= 1) s += __shfl_xor_sync(0xffffffffu, s, o);
    float inv = 1.f / s;
    __syncwarp();
    // aggregation: 32 thr x float2 (covers 64 cols), 8 chains
    int f2 = lane << 1;
    const float* base = g_Wh2 + f2;
    const int* cp = sc[grp];
    const float* wp = sw[grp];
    float2 a0 = {0,0}, a1 = {0,0}, a2 = {0,0}, a3 = {0,0};
    float2 a4 = {0,0}, a5 = {0,0}, a6 = {0,0}, a7 = {0,0};
    int j = 0;
    for (; j + 8 <= deg; j += 8) {
        float2 v0 = *(const float2*)(base + (size_t)cp[j + 0] * F1C);
        float2 v1 = *(const float2*)(base + (size_t)cp[j + 1] * F1C);
        float2 v2 = *(const float2*)(base + (size_t)cp[j + 2] * F1C);
        float2 v3 = *(const float2*)(base + (size_t)cp[j + 3] * F1C);
        float2 v4 = *(const float2*)(base + (size_t)cp[j + 4] * F1C);
        float2 v5 = *(const float2*)(base + (size_t)cp[j + 5] * F1C);
        float2 v6 = *(const float2*)(base + (size_t)cp[j + 6] * F1C);
        float2 v7 = *(const float2*)(base + (size_t)cp[j + 7] * F1C);
        float w0 = wp[j + 0], w1 = wp[j + 1], w2 = wp[j + 2], w3 = wp[j + 3];
        float w4 = wp[j + 4], w5 = wp[j + 5], w6 = wp[j + 6], w7 = wp[j + 7];
        a0.x += w0 * v0.x; a0.y += w0 * v0.y;
        a1.x += w1 * v1.x; a1.y += w1 * v1.y;
        a2.x += w2 * v2.x; a2.y += w2 * v2.y;
        a3.x += w3 * v3.x; a3.y += w3 * v3.y;
        a4.x += w4 * v4.x; a4.y += w4 * v4.y;
        a5.x += w5 * v5.x; a5.y += w5 * v5.y;
        a6.x += w6 * v6.x; a6.y += w6 * v6.y;
        a7.x += w7 * v7.x; a7.y += w7 * v7.y;
    }
    for (; j < deg; j++) {
        float2 v = *(const float2*)(base + (size_t)cp[j] * F1C);
        float w = wp[j];
        a0.x += w * v.x; a0.y += w * v.y;
    }
    float ox = (((a0.x + a1.x) + (a2.x + a3.x)) + ((a4.x + a5.x) + (a6.x + a7.x))) * inv;
    float oy = (((a0.y + a1.y) + (a2.y + a3.y)) + ((a4.y + a5.y) + (a6.y + a7.y))) * inv;
    sgc[grp][f2 + 0] = ox > 0.f ? ox : expm1f(ox);    // ELU
    sgc[grp][f2 + 1] = oy > 0.f ? oy : expm1f(oy);
    __syncwarp();
    // fc1: same warp, lane -> output col lane (32 outputs)
    float t = 0.f;
#pragma unroll 16
    for (int k = 0; k < F1C; k++) t += sgc[grp][k] * W1[k * F2C + lane];
    g_t1[row * F2C + lane] = t;
}

// ---------------- h1 = relu(adj@t1) + fc23: warp-autonomous ----------------
// warp per row; W2/W3 via L1 (no smem weights, no block barriers).
__global__ void k_spmm_fc23(const float* __restrict__ W2,
                            const float* __restrict__ W3) {
    __shared__ float sh[8][F2C];
    int tid = threadIdx.x;                            // 256 threads, 8 rows
    int wid = tid >> 5, lane = tid & 31;
    int row = blockIdx.x * 8 + wid;
    int deg = g_deg[row];
    const int* cp = g_cols + row * MAXD;
    float a0 = 0.f, a1 = 0.f, a2 = 0.f, a3 = 0.f;
    float a4 = 0.f, a5 = 0.f, a6 = 0.f, a7 = 0.f;
    int j = 0;
    for (; j + 8 <= deg; j += 8) {
        a0 += g_t1[cp[j + 0] * F2C + lane];
        a1 += g_t1[cp[j + 1] * F2C + lane];
        a2 += g_t1[cp[j + 2] * F2C + lane];
        a3 += g_t1[cp[j + 3] * F2C + lane];
        a4 += g_t1[cp[j + 4] * F2C + lane];
        a5 += g_t1[cp[j + 5] * F2C + lane];
        a6 += g_t1[cp[j + 6] * F2C + lane];
        a7 += g_t1[cp[j + 7] * F2C + lane];
    }
    for (; j < deg; j++) a0 += g_t1[cp[j] * F2C + lane];
    sh[wid][lane] = fmaxf((((a0 + a1) + (a2 + a3)) + ((a4 + a5) + (a6 + a7))), 0.f);
    __syncwarp();
    // fc23 by the same warp: lane<16 -> t2 col lane; lane>=16 -> t3 col lane-16
    int f = lane & 15;
    const float* w = (lane < 16) ? W2 : W3;
    float v = 0.f;
#pragma unroll 8
    for (int k = 0; k < F2C; k++) v += sh[wid][k] * w[k * F3C + f];
    float* dst = (lane < 16) ? g_t2 : g_t3;
    dst[row * F3C + f] = v;
}

// ---------------- mu/logvar spmm + reparameterize: warp-autonomous ---------
// warp per row; lanes 0-15 accumulate mu, 16-31 lv; shfl exchange for z.
__global__ void k_spmm_reparam(const float* __restrict__ eps,
                               float* __restrict__ out_mu,
                               float* __restrict__ out_lv) {
    int tid = threadIdx.x;                            // 256 threads, 8 rows
    int wid = tid >> 5, lane = tid & 31;
    int row = blockIdx.x * 8 + wid;
    int f = lane & 15;
    const float* src = (lane < 16) ? g_t2 : g_t3;
    int deg = g_deg[row];
    const int* cp = g_cols + row * MAXD;
    const float* base = src + f;
    float a0 = 0.f, a1 = 0.f, a2 = 0.f, a3 = 0.f;
    int j = 0;
    for (; j + 4 <= deg; j += 4) {
        a0 += base[cp[j + 0] * F3C];
        a1 += base[cp[j + 1] * F3C];
        a2 += base[cp[j + 2] * F3C];
        a3 += base[cp[j + 3] * F3C];
    }
    for (; j < deg; j++) a0 += base[cp[j] * F3C];
    float val = (a0 + a1) + (a2 + a3);
    float other = __shfl_xor_sync(0xffffffffu, val, 16);
    int o = row * F3C + f;
    if (lane < 16) {
        out_mu[o] = val;                              // val = mu, other = lv
        g_z[o] = eps[o] * expf(other) + val;
    } else {
        out_lv[o] = val;                              // val = lv
    }
}

// ---------------- adj_rec = z @ z^T (64x64 tile, K=16, write-bound) --------
__global__ void k_zzT(float* __restrict__ out) {
    __shared__ float sa[64][17];
    __shared__ float sb[64][17];
    int bi = blockIdx.y << 6, bj = blockIdx.x << 6;
    int tid = threadIdx.x;
    int r = tid >> 2, q = (tid & 3) << 2;
    float4 va = *(const float4*)(g_z + ((bi + r) << 4) + q);
    sa[r][q + 0] = va.x; sa[r][q + 1] = va.y; sa[r][q + 2] = va.z; sa[r][q + 3] = va.w;
    float4 vb = *(const float4*)(g_z + ((bj + r) << 4) + q);
    sb[r][q + 0] = vb.x; sb[r][q + 1] = vb.y; sb[r][q + 2] = vb.z; sb[r][q + 3] = vb.w;
    __syncthreads();
    int ty = tid >> 4, tx = tid & 15;
    float acc[4][4] = {};
#pragma unroll
    for (int k = 0; k < 16; k++) {
        float a0 = sa[ty * 4 + 0][k], a1 = sa[ty * 4 + 1][k];
        float a2 = sa[ty * 4 + 2][k], a3 = sa[ty * 4 + 3][k];
        float b0 = sb[tx * 4 + 0][k], b1 = sb[tx * 4 + 1][k];
        float b2 = sb[tx * 4 + 2][k], b3 = sb[tx * 4 + 3][k];
        acc[0][0] += a0 * b0; acc[0][1] += a0 * b1; acc[0][2] += a0 * b2; acc[0][3] += a0 * b3;
        acc[1][0] += a1 * b0; acc[1][1] += a1 * b1; acc[1][2] += a1 * b2; acc[1][3] += a1 * b3;
        acc[2][0] += a2 * b0; acc[2][1] += a2 * b1; acc[2][2] += a2 * b2; acc[2][3] += a2 * b3;
        acc[3][0] += a3 * b0; acc[3][1] += a3 * b1; acc[3][2] += a3 * b2; acc[3][3] += a3 * b3;
    }
#pragma unroll
    for (int i = 0; i < 4; i++) {
        float4 v = make_float4(acc[i][0], acc[i][1], acc[i][2], acc[i][3]);
        __stcs((float4*)(out + (size_t)(bi + ty * 4 + i) * NN + bj + (tx << 2)), v);
    }
}

// ---------------- launch ----------------------------------------------------
extern "C" void kernel_launch(void* const* d_in, const int* in_sizes, int n_in,
                              void* d_out, int out_size) {
    const float* x       = (const float*)d_in[0];
    const float* adj     = (const float*)d_in[1];
    const float* W_heads = (const float*)d_in[2];
    const float* a_heads = (const float*)d_in[3];
    const float* W_att   = (const float*)d_in[4];
    const float* a_att   = (const float*)d_in[5];
    const float* W1      = (const float*)d_in[6];
    const float* W2      = (const float*)d_in[7];
    const float* W3      = (const float*)d_in[8];
    const float* eps     = (const float*)d_in[9];
    float* out = (float*)d_out;
    float* out_mu = out + (size_t)NN * NN;
    float* out_lv = out_mu + (size_t)NN * F3C;

    k_build_gemm1<<<768, 256>>>(adj, x, W_heads, a_heads);  // overlap build + GEMM1
    k_gat1<<<NN / 2, 256>>>();
    k_gemm2<<<NN / 8, 128>>>(W_att, a_att);
    k_gat2_fc1<<<NN / 4, 128>>>(W1);
    k_spmm_fc23<<<NN / 8, 256>>>(W2, W3);
    k_spmm_reparam<<<NN / 8, 256>>>(eps, out_mu, out_lv);
    k_zzT<<<dim3(NN / 64, NN / 64), 256>>>(out);
}